// round 1
// baseline (speedup 1.0000x reference)
#include <cuda_runtime.h>
#include <cuda_bf16.h>

#define TLEN 2048
#define CH 32
#define NC (TLEN / CH)          // 64 chunks per sequence
#define BPB 2                   // batches per block
#define NTHREADS (NC * BPB)     // 128
#define SU_PITCH (TLEN + (TLEN >> 5))  // 2112 floats, swizzled pitch

// Swizzle: phys(t) = t + t/32. Chunk-strided reads (stride 32 floats) land on
// distinct banks; coalesced loads/stores over consecutive t stay conflict-free.
__device__ __forceinline__ int swz(int t) { return t + (t >> 5); }

__global__ __launch_bounds__(NTHREADS) void physics_scan_kernel(
    const float* __restrict__ u,
    const float* __restrict__ p_dt, const float* __restrict__ p_m,
    const float* __restrict__ p_c,  const float* __restrict__ p_k,
    const float* __restrict__ p_im, const float* __restrict__ p_is,
    const float* __restrict__ p_om, const float* __restrict__ p_os,
    float* __restrict__ out, int Bsz)
{
    __shared__ float  su[BPB][SU_PITCH];
    __shared__ float2 soff[BPB][NC];
    __shared__ float2 sstart[BPB][NC];

    const int tid = threadIdx.x;
    const int lb  = tid / NC;   // local batch within block
    const int c   = tid % NC;   // chunk id

    // Runtime scalars (device-resident; broadcast L1 hits)
    const float dt = *p_dt, m = *p_m, cc = *p_c, k = *p_k;
    const float in_mean = *p_im, in_std = *p_is;
    const float out_mean = *p_om, out_std = *p_os;
    const float inv_m = 1.0f / m;
    const float ios   = 1.0f / out_std;
    const float a1 = -k * inv_m;          // coeff of x in acc
    const float a2 = -cc * inv_m;         // coeff of v in acc
    const float s1 = in_std * inv_m;      // g = u*s1 + s0  (= u_p/m)
    const float s0 = in_mean * inv_m;
    const float q1 = a1 * ios, q2 = a2 * ios, q0 = -out_mean * ios;

    const size_t gbase = (size_t)blockIdx.x * BPB * TLEN;

    // ---- Stage u into SMEM, coalesced float4, swizzled ----
    const float4* gu = reinterpret_cast<const float4*>(u + gbase);
    #pragma unroll
    for (int j = tid; j < BPB * TLEN / 4; j += NTHREADS) {
        float4 v4 = gu[j];
        int lt = j * 4;
        int bb = lt / TLEN, t0 = lt % TLEN;
        int p = swz(t0);  // t0 % 4 == 0, so the 4 elements stay in one 32-group
        su[bb][p]     = v4.x;
        su[bb][p + 1] = v4.y;
        su[bb][p + 2] = v4.z;
        su[bb][p + 3] = v4.w;
    }
    __syncthreads();

    // ---- Pass 1: per-chunk affine offset (recurrence from zero state) ----
    const int base = c * CH;
    float x = 0.0f, v = 0.0f;
    #pragma unroll 8
    for (int i = 0; i < CH; i++) {
        float g   = fmaf(su[lb][swz(base + i)], s1, s0);
        float acc = fmaf(a1, x, fmaf(a2, v, g));
        float xn  = fmaf(dt, v, x);
        v = fmaf(dt, acc, v);
        x = xn;
    }
    soff[lb][c] = make_float2(x, v);
    __syncthreads();

    // ---- Combine: sequential scan over NC chunk offsets (1 thread / batch) ----
    if (c == 0) {
        // M = A^CH via 5 squarings (CH = 32)
        float m11 = 1.0f, m12 = dt;
        float m21 = dt * a1, m22 = 1.0f + dt * a2;
        #pragma unroll
        for (int s = 0; s < 5; s++) {
            float n11 = m11 * m11 + m12 * m21;
            float n12 = m11 * m12 + m12 * m22;
            float n21 = m21 * m11 + m22 * m21;
            float n22 = m21 * m12 + m22 * m22;
            m11 = n11; m12 = n12; m21 = n21; m22 = n22;
        }
        float sx = 0.0f, sv = 0.0f;
        #pragma unroll 1
        for (int j = 0; j < NC; j++) {
            sstart[lb][j] = make_float2(sx, sv);
            float2 o = soff[lb][j];
            float nx = fmaf(m11, sx, fmaf(m12, sv, o.x));
            float nv = fmaf(m21, sx, fmaf(m22, sv, o.y));
            sx = nx; sv = nv;
        }
    }
    __syncthreads();

    // ---- Pass 2: replay chunk from true start state, write y in-place ----
    float2 st = sstart[lb][c];
    x = st.x; v = st.y;
    #pragma unroll 8
    for (int i = 0; i < CH; i++) {
        int p = swz(base + i);
        float g   = fmaf(su[lb][p], s1, s0);
        float acc = fmaf(a1, x, fmaf(a2, v, g));
        float xn  = fmaf(dt, v, x);
        v = fmaf(dt, acc, v);
        x = xn;
        // y = ((u_p - c*v' - k*x')/m - out_mean)/out_std
        float y = fmaf(q1, x, fmaf(q2, v, fmaf(ios, g, q0)));
        su[lb][p] = y;
    }
    // Final state (chunk NC-1 thread holds s_T)
    if (c == NC - 1) {
        float2* stout = reinterpret_cast<float2*>(out + (size_t)Bsz * TLEN);
        stout[blockIdx.x * BPB + lb] = make_float2(x, v);
    }
    __syncthreads();

    // ---- Coalesced writeout of y ----
    float4* gy = reinterpret_cast<float4*>(out + gbase);
    #pragma unroll
    for (int j = tid; j < BPB * TLEN / 4; j += NTHREADS) {
        int lt = j * 4;
        int bb = lt / TLEN, t0 = lt % TLEN;
        int p = swz(t0);
        gy[j] = make_float4(su[bb][p], su[bb][p + 1], su[bb][p + 2], su[bb][p + 3]);
    }
}

extern "C" void kernel_launch(void* const* d_in, const int* in_sizes, int n_in,
                              void* d_out, int out_size) {
    const float* u = (const float*)d_in[0];
    int Bsz = in_sizes[0] / TLEN;   // u is (B, T, 1) contiguous
    dim3 grid(Bsz / BPB);
    physics_scan_kernel<<<grid, NTHREADS>>>(
        u,
        (const float*)d_in[1], (const float*)d_in[2], (const float*)d_in[3],
        (const float*)d_in[4], (const float*)d_in[5], (const float*)d_in[6],
        (const float*)d_in[7], (const float*)d_in[8],
        (float*)d_out, Bsz);
}

// round 4
// speedup vs baseline: 1.2327x; 1.2327x over previous
#include <cuda_runtime.h>
#include <cuda_bf16.h>

#define TLEN 2048
#define CH 32
#define NC 64                       // chunks per sequence
#define BPB 2                       // batches per block
#define NTHREADS 128
#define CPITCH 36                   // floats per chunk in smem (32 + 4 pad -> conflict-free float4)
#define SU_PITCH (NC * CPITCH)      // 2304 floats per batch row

// physical smem index for logical time t: chunk-padded layout
__device__ __forceinline__ int swz(int t) { return t + ((t >> 5) << 2); }

struct M2 { float a, b, c, d; };
__device__ __forceinline__ M2 mmul(M2 X, M2 Y) {   // X*Y
    M2 r;
    r.a = fmaf(X.a, Y.a, X.b * Y.c);
    r.b = fmaf(X.a, Y.b, X.b * Y.d);
    r.c = fmaf(X.c, Y.a, X.d * Y.c);
    r.d = fmaf(X.c, Y.b, X.d * Y.d);
    return r;
}

__global__ __launch_bounds__(NTHREADS) void physics_scan_kernel(
    const float* __restrict__ u,
    const float* __restrict__ p_dt, const float* __restrict__ p_m,
    const float* __restrict__ p_c,  const float* __restrict__ p_k,
    const float* __restrict__ p_im, const float* __restrict__ p_is,
    const float* __restrict__ p_om, const float* __restrict__ p_os,
    float* __restrict__ out, int Bsz)
{
    __shared__ float  su[BPB][SU_PITCH];
    __shared__ float2 sstart[BPB][NC];
    __shared__ float2 sab[CH];          // (alpha_i, beta_i) = (q1,q2)*A^{i+1}
    __shared__ float2 swtot[BPB];       // first-half-warp inclusive totals

    const int tid  = threadIdx.x;
    const int lane = tid & 31;
    const int wrp  = tid >> 5;          // 0..3
    const int lb   = tid >> 6;          // batch within block
    const int h    = (tid >> 5) & 1;    // which half of the 64 chunks
    const int c    = (h << 5) + lane;   // chunk id 0..63

    const float dt = *p_dt, m = *p_m, cc = *p_c, k = *p_k;
    const float in_mean = *p_im, in_std = *p_is;
    const float out_mean = *p_om, out_std = *p_os;
    const float inv_m = 1.0f / m;
    const float ios   = 1.0f / out_std;
    const float a1 = -k * inv_m;
    const float a2 = -cc * inv_m;
    const float s1 = in_std * inv_m;
    const float s0 = in_mean * inv_m;
    const float q1 = a1 * ios, q2 = a2 * ios, q0 = -out_mean * ios;

    M2 A; A.a = 1.0f; A.b = dt; A.c = dt * a1; A.d = 1.0f + dt * a2;

    const size_t gbase = (size_t)blockIdx.x * (BPB * TLEN);

    // ---- Stage u into smem (coalesced LDG.128 -> conflict-free STS.128) ----
    const float4* gu = reinterpret_cast<const float4*>(u + gbase);
    #pragma unroll
    for (int j = 0; j < (BPB * TLEN / 4) / NTHREADS; j++) {
        int jj = j * NTHREADS + tid;
        float4 v4 = gu[jj];
        int lt = jj << 2;
        int bb = lt >> 11;
        int t0 = lt & (TLEN - 1);
        *reinterpret_cast<float4*>(&su[bb][swz(t0)]) = v4;
    }

    // ---- (alpha,beta) table: lane i of warp 0 computes (q1,q2)*A^{i+1} ----
    if (wrp == 0) {
        M2 Q = A;
        M2 M; M.a = 1.f; M.b = 0.f; M.c = 0.f; M.d = 1.f;
        int e = lane + 1;
        #pragma unroll
        for (int b2 = 0; b2 < 6; b2++) {
            if (e & (1 << b2)) M = mmul(Q, M);
            if (b2 < 5) Q = mmul(Q, Q);
        }
        sab[lane] = make_float2(fmaf(q1, M.a, q2 * M.c),
                                fmaf(q1, M.b, q2 * M.d));
    }
    __syncthreads();

    // ---- Pass 1: chunk recurrence from zero state; y0 written in-place ----
    const int p0 = c * CPITCH;
    float* rowp = su[lb];
    float x = 0.0f, v = 0.0f;
    #pragma unroll
    for (int i4 = 0; i4 < 8; i4++) {
        float4 uu = *reinterpret_cast<float4*>(&rowp[p0 + (i4 << 2)]);
        float4 yy;
        {
            float g = fmaf(uu.x, s1, s0);
            float acc = fmaf(a1, x, fmaf(a2, v, g));
            float xn = fmaf(dt, v, x); v = fmaf(dt, acc, v); x = xn;
            yy.x = fmaf(q1, x, fmaf(q2, v, fmaf(ios, g, q0)));
        }
        {
            float g = fmaf(uu.y, s1, s0);
            float acc = fmaf(a1, x, fmaf(a2, v, g));
            float xn = fmaf(dt, v, x); v = fmaf(dt, acc, v); x = xn;
            yy.y = fmaf(q1, x, fmaf(q2, v, fmaf(ios, g, q0)));
        }
        {
            float g = fmaf(uu.z, s1, s0);
            float acc = fmaf(a1, x, fmaf(a2, v, g));
            float xn = fmaf(dt, v, x); v = fmaf(dt, acc, v); x = xn;
            yy.z = fmaf(q1, x, fmaf(q2, v, fmaf(ios, g, q0)));
        }
        {
            float g = fmaf(uu.w, s1, s0);
            float acc = fmaf(a1, x, fmaf(a2, v, g));
            float xn = fmaf(dt, v, x); v = fmaf(dt, acc, v); x = xn;
            yy.w = fmaf(q1, x, fmaf(q2, v, fmaf(ios, g, q0)));
        }
        *reinterpret_cast<float4*>(&rowp[p0 + (i4 << 2)]) = yy;
    }

    // ---- Power chain: P[s] = (A^32)^(2^s) ----
    M2 P[5];
    {
        M2 Q = A;
        #pragma unroll
        for (int s = 0; s < 5; s++) Q = mmul(Q, Q);   // A^32
        P[0] = Q;
        #pragma unroll
        for (int s = 1; s < 5; s++) P[s] = mmul(P[s - 1], P[s - 1]);
    }
    M2 P5 = mmul(P[4], P[4]);                          // (A^32)^32

    // ---- Warp Kogge-Stone scan of chunk offsets (matrix is lane-common) ----
    float bx = x, bv = v;
    #pragma unroll
    for (int s = 0; s < 5; s++) {
        int d = 1 << s;
        float ox = __shfl_up_sync(0xffffffffu, bx, d);
        float ov = __shfl_up_sync(0xffffffffu, bv, d);
        if (lane >= d) {
            bx = fmaf(P[s].a, ox, fmaf(P[s].b, ov, bx));
            bv = fmaf(P[s].c, ox, fmaf(P[s].d, ov, bv));
        }
    }
    float ex = __shfl_up_sync(0xffffffffu, bx, 1);
    float ev = __shfl_up_sync(0xffffffffu, bv, 1);
    if (lane == 0) { ex = 0.0f; ev = 0.0f; }

    if (h == 0 && lane == 31) swtot[lb] = make_float2(bx, bv);
    __syncthreads();

    // ---- Cross-warp fix-up + store per-chunk start states ----
    float sx = ex, sv = ev;
    if (h == 1) {
        float2 t = swtot[lb];
        float wx = t.x, wv = t.y;     // (A^32)^lane * s_in via bit products
        #pragma unroll
        for (int b2 = 0; b2 < 5; b2++) {
            if (lane & (1 << b2)) {
                float nx = fmaf(P[b2].a, wx, P[b2].b * wv);
                float nv = fmaf(P[b2].c, wx, P[b2].d * wv);
                wx = nx; wv = nv;
            }
        }
        sx += wx; sv += wv;
        if (lane == 31) {             // final state s_T = b_inc + (A^32)^32 * s_in
            float fx = fmaf(P5.a, t.x, fmaf(P5.b, t.y, bx));
            float fv = fmaf(P5.c, t.x, fmaf(P5.d, t.y, bv));
            float2* stout = reinterpret_cast<float2*>(out + (size_t)Bsz * TLEN);
            stout[blockIdx.x * BPB + lb] = make_float2(fx, fv);
        }
    }
    sstart[lb][c] = make_float2(sx, sv);
    __syncthreads();

    // ---- Writeout with fused affine correction: y = y0 + (a,b)·s_start ----
    float4* gy = reinterpret_cast<float4*>(out + gbase);
    const float4* abv = reinterpret_cast<const float4*>(sab);
    #pragma unroll
    for (int j = 0; j < (BPB * TLEN / 4) / NTHREADS; j++) {
        int jj = j * NTHREADS + tid;
        int lt = jj << 2;
        int bb = lt >> 11;
        int t0 = lt & (TLEN - 1);
        float4 y0 = *reinterpret_cast<const float4*>(&su[bb][swz(t0)]);
        int ch = t0 >> 5;
        int i0 = t0 & 31;
        float2 ss  = sstart[bb][ch];
        float4 ab01 = abv[i0 >> 1];
        float4 ab23 = abv[(i0 >> 1) + 1];
        float4 yy;
        yy.x = fmaf(ab01.x, ss.x, fmaf(ab01.y, ss.y, y0.x));
        yy.y = fmaf(ab01.z, ss.x, fmaf(ab01.w, ss.y, y0.y));
        yy.z = fmaf(ab23.x, ss.x, fmaf(ab23.y, ss.y, y0.z));
        yy.w = fmaf(ab23.z, ss.x, fmaf(ab23.w, ss.y, y0.w));
        gy[jj] = yy;
    }
}

extern "C" void kernel_launch(void* const* d_in, const int* in_sizes, int n_in,
                              void* d_out, int out_size) {
    const float* u = (const float*)d_in[0];
    int Bsz = in_sizes[0] / TLEN;
    dim3 grid(Bsz / BPB);
    physics_scan_kernel<<<grid, NTHREADS>>>(
        u,
        (const float*)d_in[1], (const float*)d_in[2], (const float*)d_in[3],
        (const float*)d_in[4], (const float*)d_in[5], (const float*)d_in[6],
        (const float*)d_in[7], (const float*)d_in[8],
        (float*)d_out, Bsz);
}